// round 4
// baseline (speedup 1.0000x reference)
#include <cuda_runtime.h>
#include <math.h>

// Problem constants
#define Bc 32
#define Nc 256
#define Tc 64
#define Mc 64
#define Hc 512
#define Wc 512
#define COL_THRESH 0.5f
#define CAND_PER_BLK 4   // candidates per block in kernel 1

// Scratch for raw per-(b,n) scores: [f_dis, f_pg, min_col_sq, f_dac]
__device__ float4 g_scratch[Bc * Nc];

// ---------------------------------------------------------------------------
// Kernel 1: per-(b,n) raw score computation.
// grid = (N/CAND_PER_BLK, B), block = 64*CAND_PER_BLK threads.
// Each 64-thread group handles one candidate (one thread per timestep t).
// ---------------------------------------------------------------------------
__global__ __launch_bounds__(64 * CAND_PER_BLK) void score_kernel(
    const float* __restrict__ traj,     // (B,N,T,2)
    const float* __restrict__ goal,     // (B,2)
    const float* __restrict__ gt,       // (B,T,2)
    const float* __restrict__ obs,      // (B,M,2)
    const float* __restrict__ da)       // (B,H,W)
{
    const int b    = blockIdx.y;
    const int tid  = threadIdx.x;
    const int c    = tid >> 6;                      // candidate slot 0..3
    const int t    = tid & 63;                      // timestep 0..63
    const int n    = blockIdx.x * CAND_PER_BLK + c; // candidate index

    __shared__ float4 s_obs[Mc];   // (-2*ox, -2*oy, |o|^2, pad)
    __shared__ float2 s_gt[Tc];
    __shared__ float  s_red[CAND_PER_BLK][3][2];
    __shared__ float  s_pg[CAND_PER_BLK];

    // Stage transformed obstacles + gt for this batch into shared (once/block)
    if (tid < Mc) {
        float2 o = ((const float2*)obs)[b * Mc + tid];
        float o2 = fmaf(o.x, o.x, o.y * o.y);
        s_obs[tid] = make_float4(-2.0f * o.x, -2.0f * o.y, o2, 0.0f);
    } else if (tid < Mc + Tc) {
        s_gt[tid - Mc] = ((const float2*)gt)[b * Tc + (tid - Mc)];
    }
    __syncthreads();

    // My trajectory point (coalesced float2 load)
    const float2 p = ((const float2*)traj)[((size_t)(b * Nc + n)) * Tc + t];

    // --- distance-to-GT term ---
    const float2 g = s_gt[t];
    float dxg = p.x - g.x, dyg = p.y - g.y;
    float dis = sqrtf(fmaf(dxg, dxg, dyg * dyg));

    // --- progress term (endpoint only) ---
    if (t == Tc - 1) {
        const float2 gl = ((const float2*)goal)[b];
        float ex = p.x - gl.x, ey = p.y - gl.y;
        s_pg[c] = sqrtf(fmaf(ex, ex, ey * ey));
    }

    // --- collision term: min over M of (|o|^2 - 2 p.o); add |p|^2 at the end
    const float BIG = 3.402823466e+38f;
    float m0 = BIG, m1 = BIG, m2 = BIG, m3 = BIG;
#pragma unroll
    for (int m = 0; m < Mc; m += 4) {
        float4 o0 = s_obs[m + 0];
        float4 o1 = s_obs[m + 1];
        float4 o2 = s_obs[m + 2];
        float4 o3 = s_obs[m + 3];
        m0 = fminf(m0, fmaf(p.y, o0.y, fmaf(p.x, o0.x, o0.z)));
        m1 = fminf(m1, fmaf(p.y, o1.y, fmaf(p.x, o1.x, o1.z)));
        m2 = fminf(m2, fmaf(p.y, o2.y, fmaf(p.x, o2.x, o2.z)));
        m3 = fminf(m3, fmaf(p.y, o3.y, fmaf(p.x, o3.x, o3.z)));
    }
    float p2 = fmaf(p.x, p.x, p.y * p.y);
    float mind2 = p2 + fminf(fminf(m0, m1), fminf(m2, m3));
    mind2 = fmaxf(mind2, 0.0f);   // guard cancellation before sqrt later

    // --- DAC term: gather from drivable mask ---
    // Match jnp op order exactly: ((x + 50.0)/100.0) * (w-1), int32 trunc, clip
    int xi = (int)((p.x + 50.0f) / 100.0f * (float)(Wc - 1));
    int yi = (int)((p.y + 50.0f) / 100.0f * (float)(Hc - 1));
    xi = min(max(xi, 0), Wc - 1);
    yi = min(max(yi, 0), Hc - 1);
    float dac = 1.0f - __ldg(&da[(size_t)b * (Hc * Wc) + yi * Wc + xi]);

    // --- reduction within the 64-thread candidate group ---
#pragma unroll
    for (int off = 16; off > 0; off >>= 1) {
        dis   += __shfl_xor_sync(0xFFFFFFFFu, dis, off);
        dac   += __shfl_xor_sync(0xFFFFFFFFu, dac, off);
        mind2  = fminf(mind2, __shfl_xor_sync(0xFFFFFFFFu, mind2, off));
    }
    const int lane = t & 31, w = t >> 5;   // warp-within-candidate: 0 or 1
    if (lane == 0) {
        s_red[c][0][w] = dis;
        s_red[c][1][w] = mind2;
        s_red[c][2][w] = dac;
    }
    __syncthreads();

    if (t == 0) {
        float f_dis   = (s_red[c][0][0] + s_red[c][0][1]) * (1.0f / Tc);
        float mcolsq  = fminf(s_red[c][1][0], s_red[c][1][1]);
        float f_dac   = (s_red[c][2][0] + s_red[c][2][1]) * (1.0f / Tc);
        g_scratch[b * Nc + n] = make_float4(f_dis, s_pg[c], mcolsq, f_dac);
    }
}

// ---------------------------------------------------------------------------
// Kernel 2: per-batch normalize, combine, argmax, gather best trajectory.
// grid = B, block = 256 threads (one per candidate n).
// All four min/max pairs reduced in ONE shuffle tree (3 barriers total).
// Second-stage reductions are executed by ALL 32 lanes of warp 0 (lanes 8-31
// hold redundant copies via lane&7 indexing) so every __shfl_xor_sync with a
// full mask is convergent — the R3 hang came from gating to lane<8.
// ---------------------------------------------------------------------------
__global__ __launch_bounds__(256) void select_kernel(
    const float* __restrict__ traj,  // (B,N,T,2)
    float* __restrict__ out)         // [B*T*2 best | B*N scores]
{
    const int b = blockIdx.x;
    const int n = threadIdx.x;  // 0..255
    const int lane = n & 31, w = n >> 5;

    __shared__ float s_mn[8][4], s_mx[8][4];
    __shared__ float s_fmn[4], s_fmx[4];
    __shared__ float s_bs[8];
    __shared__ int   s_bi[8];
    __shared__ int   s_best;

    float4 raw = g_scratch[b * Nc + n];
    float mcol = sqrtf(raw.z);
    float tt   = mcol - COL_THRESH;
    float v[4];
    v[0] = raw.x;               // f_dis
    v[1] = raw.y;               // f_pg
    v[2] = expf(-(tt * tt));    // f_col
    v[3] = raw.w;               // f_dac

    // --- combined 8-value warp reduction (4 mins + 4 maxes) ---
    float mn4[4], mx4[4];
#pragma unroll
    for (int i = 0; i < 4; i++) { mn4[i] = v[i]; mx4[i] = v[i]; }
#pragma unroll
    for (int off = 16; off > 0; off >>= 1) {
#pragma unroll
        for (int i = 0; i < 4; i++) {
            mn4[i] = fminf(mn4[i], __shfl_xor_sync(0xFFFFFFFFu, mn4[i], off));
            mx4[i] = fmaxf(mx4[i], __shfl_xor_sync(0xFFFFFFFFu, mx4[i], off));
        }
    }
    if (lane == 0) {
#pragma unroll
        for (int i = 0; i < 4; i++) { s_mn[w][i] = mn4[i]; s_mx[w][i] = mx4[i]; }
    }
    __syncthreads();
    if (w == 0) {   // FULL warp participates — convergent shuffles
#pragma unroll
        for (int i = 0; i < 4; i++) {
            mn4[i] = s_mn[lane & 7][i];
            mx4[i] = s_mx[lane & 7][i];
        }
#pragma unroll
        for (int off = 4; off > 0; off >>= 1) {
#pragma unroll
            for (int i = 0; i < 4; i++) {
                mn4[i] = fminf(mn4[i], __shfl_xor_sync(0xFFFFFFFFu, mn4[i], off));
                mx4[i] = fmaxf(mx4[i], __shfl_xor_sync(0xFFFFFFFFu, mx4[i], off));
            }
        }
        if (lane == 0) {
#pragma unroll
            for (int i = 0; i < 4; i++) { s_fmn[i] = mn4[i]; s_fmx[i] = mx4[i]; }
        }
    }
    __syncthreads();

    float score = 0.0f;
#pragma unroll
    for (int i = 0; i < 4; i++) {
        float d = s_fmx[i] - s_fmn[i];
        d = (d == 0.0f) ? 1.0f : d;
        score += (v[i] - s_fmn[i]) / d;
    }
    score = -score;

    // scores output region starts after best_trajectory block (B*T*2 floats)
    float* out_scores = out + (Bc * Tc * 2);
    out_scores[b * Nc + n] = score;

    // --- argmax with first-index tie-break (matches jnp.argmax) ---
    float bs = score;
    int   bi = n;
#pragma unroll
    for (int off = 16; off > 0; off >>= 1) {
        float os = __shfl_xor_sync(0xFFFFFFFFu, bs, off);
        int   oi = __shfl_xor_sync(0xFFFFFFFFu, bi, off);
        if (os > bs || (os == bs && oi < bi)) { bs = os; bi = oi; }
    }
    if (lane == 0) { s_bs[w] = bs; s_bi[w] = bi; }
    __syncthreads();
    if (w == 0) {   // FULL warp participates — convergent shuffles
        bs = s_bs[lane & 7];
        bi = s_bi[lane & 7];
#pragma unroll
        for (int off = 4; off > 0; off >>= 1) {
            float os = __shfl_xor_sync(0xFFFFFFFFu, bs, off);
            int   oi = __shfl_xor_sync(0xFFFFFFFFu, bi, off);
            if (os > bs || (os == bs && oi < bi)) { bs = os; bi = oi; }
        }
        if (lane == 0) s_best = bi;
    }
    __syncthreads();

    // --- copy best trajectory: T*2 = 128 floats = 64 float2 ---
    const int best = s_best;
    if (n < Tc) {
        ((float2*)out)[b * Tc + n] =
            ((const float2*)traj)[((size_t)(b * Nc + best)) * Tc + n];
    }
}

// ---------------------------------------------------------------------------
// Launch
// ---------------------------------------------------------------------------
extern "C" void kernel_launch(void* const* d_in, const int* in_sizes, int n_in,
                              void* d_out, int out_size)
{
    const float* traj = (const float*)d_in[0];   // (B,N,T,2)
    const float* goal = (const float*)d_in[1];   // (B,2)
    const float* gt   = (const float*)d_in[2];   // (B,T,2)
    const float* obs  = (const float*)d_in[3];   // (B,M,2)
    const float* da   = (const float*)d_in[4];   // (B,H,W)
    float* out = (float*)d_out;

    dim3 g1(Nc / CAND_PER_BLK, Bc);
    score_kernel<<<g1, 64 * CAND_PER_BLK>>>(traj, goal, gt, obs, da);
    select_kernel<<<Bc, 256>>>(traj, out);
}